// round 13
// baseline (speedup 1.0000x reference)
#include <cuda_runtime.h>
#include <cstdint>
#include <cstddef>

#define KDIM 512
#define NRE 257
#define NTOT 514
#define NPAD 576
#define BM 128
#define BK 32
#define STAGES 3
#define THREADS 256
#define A_STAGE_BYTES (BM * BK * 4)                 // 16384
#define B_STAGE_BYTES_MAX (64 * BK * 4)             // 8192 (NB=4 path)
#define STAGE_BYTES_MAX (A_STAGE_BYTES + B_STAGE_BYTES_MAX)
#define SMEM_BYTES (STAGES * STAGE_BYTES_MAX)       // 73728
#define STG_STRIDE 68

// Pre-converted, zero-padded, k-pair-permuted B (tf32 bits).
// Row n, k8 group: order [k0,k4,k1,k5,k2,k6,k3,k7] so thread t's pair (k_t, k_{t+4}) is 8B.
__device__ uint32_t g_Bcvt[NPAD * KDIM];

__device__ __forceinline__ void mma_tf32(float& c0, float& c1, float& c2, float& c3,
                                         uint32_t a0, uint32_t a1, uint32_t a2, uint32_t a3,
                                         uint32_t b0, uint32_t b1) {
    asm volatile(
        "mma.sync.aligned.m16n8k8.row.col.f32.tf32.tf32.f32 "
        "{%0,%1,%2,%3}, {%4,%5,%6,%7}, {%8,%9}, {%0,%1,%2,%3};\n"
        : "+f"(c0), "+f"(c1), "+f"(c2), "+f"(c3)
        : "r"(a0), "r"(a1), "r"(a2), "r"(a3), "r"(b0), "r"(b1));
}

__device__ __forceinline__ uint32_t f2tf32(float f) {
    uint32_t r;
    asm volatile("cvt.rna.tf32.f32 %0, %1;\n" : "=r"(r) : "f"(f));
    return r;
}

__device__ __forceinline__ uint32_t f2tf32_u(uint32_t fbits) {
    uint32_t r;
    asm volatile("cvt.rna.tf32.f32 %0, %1;\n" : "=r"(r) : "r"(fbits));
    return r;
}

__device__ __forceinline__ void cpa16(uint32_t dst, const void* src) {
    asm volatile("cp.async.cg.shared.global [%0], [%1], 16;" :: "r"(dst), "l"(src));
}

template <int N>
__device__ __forceinline__ void cpa_wait() {
    asm volatile("cp.async.wait_group %0;" :: "n"(N) : "memory");
}

// ---- pre-kernel: padded, permuted tf32 B ----
__global__ void build_B_kernel(const float* __restrict__ MR, const float* __restrict__ MI) {
    int idx = blockIdx.x * blockDim.x + threadIdx.x;   // 0 .. NPAD*KDIM-1
    int n = idx >> 9;
    int k = idx & 511;
    float v = 0.f;
    if (n < NRE)       v = MR[(size_t)n * KDIM + k];
    else if (n < NTOT) v = MI[(size_t)(n - NRE) * KDIM + k];
    int p = (k & ~7) | (((k & 3) << 1) | ((k >> 2) & 1));   // pair-permute within k8 group
    g_Bcvt[(size_t)n * KDIM + p] = f2tf32(v);
}

template <int NB>   // warp tile 32 x (NB*8); CTA N width = 2*NB*8
__device__ __forceinline__ void gemm_path(const float* __restrict__ X,
                                          float* __restrict__ OUT, int M,
                                          int m0, int n0, char* smem) {
    constexpr int BROWS = 2 * NB * 8;                       // 64 or 16
    constexpr int B_STAGE_BYTES = BROWS * BK * 4;
    constexpr int STAGE_BYTES = A_STAGE_BYTES + B_STAGE_BYTES;
    constexpr int B_OFF32 = A_STAGE_BYTES / 4;

    uint32_t* Ssm = (uint32_t*)smem;
    const int tid = threadIdx.x;
    const int w = tid >> 5;
    const int lane = tid & 31;
    const int wm = w >> 1;            // 0..3 : 32-row M slice
    const int wn = w & 1;             // 0..1 : NB*8-col N slice
    const int g = lane >> 2;
    const int t = lane & 3;
    const uint32_t smem_u32 = (uint32_t)__cvta_generic_to_shared(smem);

    // ---- stage loader (A + B cooperative cp.async) ----
    auto load_stage = [&](int kt, int stage) {
        const uint32_t abase = smem_u32 + stage * STAGE_BYTES;
#pragma unroll
        for (int i = 0; i < 4; i++) {
            int idx = tid + i * THREADS;      // 0..1023
            int row = idx >> 3;               // 0..127
            int ch  = idx & 7;
            uint32_t dst = abase + row * 128 + ((ch * 16) ^ ((row & 7) * 16));
            cpa16(dst, X + (size_t)(m0 + row) * KDIM + kt * BK + ch * 4);
        }
        const uint32_t bbase = abase + A_STAGE_BYTES;
#pragma unroll
        for (int i = 0; i < (BROWS * 8 + THREADS - 1) / THREADS; i++) {
            int idx = tid + i * THREADS;
            if (BROWS * 8 % THREADS == 0 || idx < BROWS * 8) {
                int row = idx >> 3;
                int ch  = idx & 7;
                int win = ch >> 1, half = ch & 1;
                uint32_t dst = bbase + row * 128 + (((win + row) & 3) << 5) + (half << 4);
                cpa16(dst, g_Bcvt + (size_t)(n0 + row) * KDIM + kt * BK + ch * 4);
            }
        }
        asm volatile("cp.async.commit_group;" ::: "memory");
    };

#pragma unroll
    for (int p = 0; p < STAGES; p++)
        load_stage(p, p);

    float acc[2][NB][4];
#pragma unroll
    for (int mb = 0; mb < 2; mb++)
#pragma unroll
        for (int nb = 0; nb < NB; nb++)
#pragma unroll
            for (int j = 0; j < 4; j++)
                acc[mb][nb][j] = 0.f;

    const int gsw = g << 2;
    int aOff[2];
#pragma unroll
    for (int mb = 0; mb < 2; mb++)
        aOff[mb] = (wm * 32 + mb * 16 + g) * 32;
    const int bBase = B_OFF32 + (wn * NB * 8 + g) * 32 + t * 2;   // + nb*256 immediate
    const int rot = g & 3;    // (wn*NB*8 + nb*8 + g) & 3 == g & 3

    // ---- mainloop: single barrier per k-tile ----
#pragma unroll 1
    for (int kt = 0; kt < KDIM / BK; kt++) {
        if (kt < KDIM / BK - 1) cpa_wait<1>();
        else                    cpa_wait<0>();
        __syncthreads();
        // refill buffer (kt-1)%3 (everyone finished it at kt-1; barrier above protects)
        if (kt >= 1 && kt + 2 < KDIM / BK)
            load_stage(kt + 2, (kt + 2) % STAGES);

        const uint32_t* sp = Ssm + (kt % STAGES) * (STAGE_BYTES / 4);
#pragma unroll
        for (int ks = 0; ks < 4; ks++) {
            const int c0 = (ks * 8 + t) ^ gsw;
            const int c1 = c0 ^ 4;
            const int woff = ((ks + rot) & 3) << 3;
            uint32_t b[NB][2];
#pragma unroll
            for (int nb = 0; nb < NB; nb++) {
                uint2 v = *(const uint2*)(sp + bBase + nb * 256 + woff);
                b[nb][0] = v.x;
                b[nb][1] = v.y;
            }
#pragma unroll
            for (int mb = 0; mb < 2; mb++) {
                const uint32_t* ap = sp + aOff[mb];
                uint32_t a0 = f2tf32_u(ap[c0]);
                uint32_t a1 = f2tf32_u(ap[c0 + 256]);   // row + 8
                uint32_t a2 = f2tf32_u(ap[c1]);
                uint32_t a3 = f2tf32_u(ap[c1 + 256]);
#pragma unroll
                for (int nb = 0; nb < NB; nb++)
                    mma_tf32(acc[mb][nb][0], acc[mb][nb][1], acc[mb][nb][2], acc[mb][nb][3],
                             a0, a1, a2, a3, b[nb][0], b[nb][1]);
            }
        }
    }

    // ---- epilogue: smem-staged, coalesced stores ----
    __syncthreads();
    float* stg = (float*)smem;     // 128 x STG_STRIDE floats = 34.8 KB
#pragma unroll
    for (int mb = 0; mb < 2; mb++) {
#pragma unroll
        for (int nb = 0; nb < NB; nb++) {
            const int row = wm * 32 + mb * 16 + g;
            const int col = wn * NB * 8 + nb * 8 + 2 * t;
            stg[row * STG_STRIDE + col]           = acc[mb][nb][0];
            stg[row * STG_STRIDE + col + 1]       = acc[mb][nb][1];
            stg[(row + 8) * STG_STRIDE + col]     = acc[mb][nb][2];
            stg[(row + 8) * STG_STRIDE + col + 1] = acc[mb][nb][3];
        }
    }
    __syncthreads();

    float* re = OUT;
    float* im = OUT + (size_t)M * NRE;
#pragma unroll
    for (int rr = 0; rr < 16; rr++) {
        const int row = w * 16 + rr;
        const size_t r = m0 + row;
#pragma unroll
        for (int c = 0; c < (BROWS + 31) / 32; c++) {
            const int cl = c * 32 + lane;
            if (BROWS % 32 == 0 || cl < BROWS) {
                const int n = n0 + cl;
                const float v = stg[row * STG_STRIDE + cl];
                if (n < NRE)       re[r * NRE + n] = v;
                else if (n < NTOT) im[r * NRE + (n - NRE)] = v;
            }
        }
    }
}

__global__ void __launch_bounds__(THREADS, 3)
rfft_wmma_kernel(const float* __restrict__ X, float* __restrict__ OUT, int M) {
    extern __shared__ __align__(1024) char smem[];
    const int m0 = blockIdx.y * BM;
    if (blockIdx.x < 8) {
        gemm_path<4>(X, OUT, M, m0, blockIdx.x * 64, smem);   // n 0..511 (all real)
    } else {
        gemm_path<1>(X, OUT, M, m0, 512, smem);               // n 512..527 (covers 512..513)
    }
}

extern "C" void kernel_launch(void* const* d_in, const int* in_sizes, int n_in,
                              void* d_out, int out_size) {
    const float* X  = (const float*)d_in[0];
    const float* MR = (const float*)d_in[1];
    const float* MI = (const float*)d_in[2];
    float* OUT = (float*)d_out;
    const int M = in_sizes[0] / KDIM;   // 128000

    build_B_kernel<<<(NPAD * KDIM) / 256, 256>>>(MR, MI);

    cudaFuncSetAttribute(rfft_wmma_kernel, cudaFuncAttributeMaxDynamicSharedMemorySize, SMEM_BYTES);
    dim3 grid(9, M / BM);   // 8 full 64-wide columns + 1 16-wide tail
    rfft_wmma_kernel<<<grid, THREADS, SMEM_BYTES>>>(X, OUT, M);
}

// round 14
// speedup vs baseline: 1.1039x; 1.1039x over previous
#include <cuda_runtime.h>
#include <cstdint>
#include <cstddef>

#define KDIM 512
#define NRE 257
#define NTOT 514
#define NPAD 576
#define BM 128
#define BK 32
#define STAGES 4
#define THREADS 256
#define A_STAGE_BYTES (BM * BK * 4)                 // 16384
#define B_STAGE_BYTES_MAX (96 * BK * 4)             // 12288 (NB=6 path)
#define STAGE_BYTES_MAX (A_STAGE_BYTES + B_STAGE_BYTES_MAX)  // 28672
#define SMEM_BYTES (STAGES * STAGE_BYTES_MAX)       // 114688
#define STG_STRIDE 100

// Pre-converted, zero-padded, k-pair-permuted B (tf32 bits).
// Row n, k8 group: order [k0,k4,k1,k5,k2,k6,k3,k7] so thread t's pair (k_t, k_{t+4}) is 8B.
__device__ uint32_t g_Bcvt[NPAD * KDIM];

__device__ __forceinline__ void mma_tf32(float& c0, float& c1, float& c2, float& c3,
                                         uint32_t a0, uint32_t a1, uint32_t a2, uint32_t a3,
                                         uint32_t b0, uint32_t b1) {
    asm volatile(
        "mma.sync.aligned.m16n8k8.row.col.f32.tf32.tf32.f32 "
        "{%0,%1,%2,%3}, {%4,%5,%6,%7}, {%8,%9}, {%0,%1,%2,%3};\n"
        : "+f"(c0), "+f"(c1), "+f"(c2), "+f"(c3)
        : "r"(a0), "r"(a1), "r"(a2), "r"(a3), "r"(b0), "r"(b1));
}

__device__ __forceinline__ uint32_t f2tf32(float f) {
    uint32_t r;
    asm volatile("cvt.rna.tf32.f32 %0, %1;\n" : "=r"(r) : "f"(f));
    return r;
}

__device__ __forceinline__ uint32_t f2tf32_u(uint32_t fbits) {
    uint32_t r;
    asm volatile("cvt.rna.tf32.f32 %0, %1;\n" : "=r"(r) : "r"(fbits));
    return r;
}

__device__ __forceinline__ void cpa16(uint32_t dst, const void* src) {
    asm volatile("cp.async.cg.shared.global [%0], [%1], 16;" :: "r"(dst), "l"(src));
}

template <int N>
__device__ __forceinline__ void cpa_wait() {
    asm volatile("cp.async.wait_group %0;" :: "n"(N) : "memory");
}

// ---- pre-kernel: padded, permuted tf32 B ----
__global__ void build_B_kernel(const float* __restrict__ MR, const float* __restrict__ MI) {
    int idx = blockIdx.x * blockDim.x + threadIdx.x;   // 0 .. NPAD*KDIM-1
    int n = idx >> 9;
    int k = idx & 511;
    float v = 0.f;
    if (n < NRE)       v = MR[(size_t)n * KDIM + k];
    else if (n < NTOT) v = MI[(size_t)(n - NRE) * KDIM + k];
    int p = (k & ~7) | (((k & 3) << 1) | ((k >> 2) & 1));   // pair-permute within k8 group
    g_Bcvt[(size_t)n * KDIM + p] = f2tf32(v);
}

template <int NB>   // warp tile 32 x (NB*8); CTA N width = 2*NB*8
__device__ __forceinline__ void gemm_path(const float* __restrict__ X,
                                          float* __restrict__ OUT, int M,
                                          int m0, int n0, char* smem) {
    constexpr int BROWS = 2 * NB * 8;                       // 96 or 48
    constexpr int B_STAGE_BYTES = BROWS * BK * 4;
    constexpr int STAGE_BYTES = A_STAGE_BYTES + B_STAGE_BYTES;
    constexpr int B_OFF32 = A_STAGE_BYTES / 4;
    constexpr int KT_END = KDIM / BK;                       // 16

    uint32_t* Ssm = (uint32_t*)smem;
    const int tid = threadIdx.x;
    const int w = tid >> 5;
    const int lane = tid & 31;
    const int wm = w >> 1;            // 0..3 : 32-row M slice
    const int wn = w & 1;             // 0..1 : NB*8-col N slice
    const int g = lane >> 2;
    const int t = lane & 3;
    const uint32_t smem_u32 = (uint32_t)__cvta_generic_to_shared(smem);

    // ---- stage loader (A + B cooperative cp.async) ----
    auto load_stage = [&](int kt, int stage) {
        const uint32_t abase = smem_u32 + stage * STAGE_BYTES;
#pragma unroll
        for (int i = 0; i < 4; i++) {
            int idx = tid + i * THREADS;      // 0..1023
            int row = idx >> 3;               // 0..127
            int ch  = idx & 7;
            uint32_t dst = abase + row * 128 + ((ch * 16) ^ ((row & 7) * 16));
            cpa16(dst, X + (size_t)(m0 + row) * KDIM + kt * BK + ch * 4);
        }
        const uint32_t bbase = abase + A_STAGE_BYTES;
#pragma unroll
        for (int i = 0; i < (BROWS * 8 + THREADS - 1) / THREADS; i++) {
            int idx = tid + i * THREADS;
            if (BROWS * 8 % THREADS == 0 || idx < BROWS * 8) {
                int row = idx >> 3;
                int ch  = idx & 7;
                int win = ch >> 1, half = ch & 1;
                uint32_t dst = bbase + row * 128 + (((win + row) & 3) << 5) + (half << 4);
                cpa16(dst, g_Bcvt + (size_t)(n0 + row) * KDIM + kt * BK + ch * 4);
            }
        }
        asm volatile("cp.async.commit_group;" ::: "memory");
    };

    // prologue: tiles 0,1,2 into slots 0,1,2
#pragma unroll
    for (int p = 0; p < 3; p++)
        load_stage(p, p);

    float acc[2][NB][4];
#pragma unroll
    for (int mb = 0; mb < 2; mb++)
#pragma unroll
        for (int nb = 0; nb < NB; nb++)
#pragma unroll
            for (int j = 0; j < 4; j++)
                acc[mb][nb][j] = 0.f;

    const int gsw = g << 2;
    int aOff[2];
#pragma unroll
    for (int mb = 0; mb < 2; mb++)
        aOff[mb] = (wm * 32 + mb * 16 + g) * 32;
    const int bBase = B_OFF32 + (wn * NB * 8 + g) * 32 + t * 2;   // + nb*256 immediate
    const int rot = g & 3;    // (wn*NB*8 + nb*8 + g) & 3 == g & 3

    // ---- mainloop: single barrier per k-tile, depth-3 prefetch ----
#pragma unroll 1
    for (int kt = 0; kt < KT_END; kt++) {
        if (kt <= KT_END - 3)      cpa_wait<2>();   // tile kt complete; kt+1,kt+2 in flight
        else if (kt == KT_END - 2) cpa_wait<1>();
        else                       cpa_wait<0>();
        __syncthreads();   // all warps: tile kt visible AND kt-1 compute finished

        // refill slot (kt+3)%4 == (kt-1)%4 with tile kt+3 (protected by barrier above)
        if (kt + 3 < KT_END)
            load_stage(kt + 3, (kt + 3) % STAGES);

        const uint32_t* sp = Ssm + (kt % STAGES) * (STAGE_BYTES / 4);
#pragma unroll
        for (int ks = 0; ks < 4; ks++) {
            const int c0 = (ks * 8 + t) ^ gsw;
            const int c1 = c0 ^ 4;
            const int woff = ((ks + rot) & 3) << 3;
            uint32_t b[NB][2];
#pragma unroll
            for (int nb = 0; nb < NB; nb++) {
                uint2 v = *(const uint2*)(sp + bBase + nb * 256 + woff);
                b[nb][0] = v.x;
                b[nb][1] = v.y;
            }
#pragma unroll
            for (int mb = 0; mb < 2; mb++) {
                const uint32_t* ap = sp + aOff[mb];
                uint32_t a0 = f2tf32_u(ap[c0]);
                uint32_t a1 = f2tf32_u(ap[c0 + 256]);   // row + 8
                uint32_t a2 = f2tf32_u(ap[c1]);
                uint32_t a3 = f2tf32_u(ap[c1 + 256]);
#pragma unroll
                for (int nb = 0; nb < NB; nb++)
                    mma_tf32(acc[mb][nb][0], acc[mb][nb][1], acc[mb][nb][2], acc[mb][nb][3],
                             a0, a1, a2, a3, b[nb][0], b[nb][1]);
            }
        }
    }

    // ---- epilogue: smem-staged, coalesced stores ----
    __syncthreads();
    float* stg = (float*)smem;     // 128 x STG_STRIDE floats = 51.2 KB
#pragma unroll
    for (int mb = 0; mb < 2; mb++) {
#pragma unroll
        for (int nb = 0; nb < NB; nb++) {
            const int row = wm * 32 + mb * 16 + g;
            const int col = wn * NB * 8 + nb * 8 + 2 * t;
            stg[row * STG_STRIDE + col]           = acc[mb][nb][0];
            stg[row * STG_STRIDE + col + 1]       = acc[mb][nb][1];
            stg[(row + 8) * STG_STRIDE + col]     = acc[mb][nb][2];
            stg[(row + 8) * STG_STRIDE + col + 1] = acc[mb][nb][3];
        }
    }
    __syncthreads();

    float* re = OUT;
    float* im = OUT + (size_t)M * NRE;
#pragma unroll
    for (int rr = 0; rr < 16; rr++) {
        const int row = w * 16 + rr;
        const size_t r = m0 + row;
#pragma unroll
        for (int c = 0; c < (BROWS + 31) / 32; c++) {
            const int cl = c * 32 + lane;
            if (BROWS % 32 == 0 || cl < BROWS) {
                const int n = n0 + cl;
                const float v = stg[row * STG_STRIDE + cl];
                if (n < NRE)       re[r * NRE + n] = v;
                else if (n < NTOT) im[r * NRE + (n - NRE)] = v;
            }
        }
    }
}

__global__ void __launch_bounds__(THREADS, 2)
rfft_wmma_kernel(const float* __restrict__ X, float* __restrict__ OUT, int M) {
    extern __shared__ __align__(1024) char smem[];
    const int m0 = blockIdx.y * BM;
    if (blockIdx.x < 5) {
        gemm_path<6>(X, OUT, M, m0, blockIdx.x * 96, smem);   // n 0..479 (all real)
    } else {
        gemm_path<3>(X, OUT, M, m0, 480, smem);               // n 480..527 (covers 480..513)
    }
}

extern "C" void kernel_launch(void* const* d_in, const int* in_sizes, int n_in,
                              void* d_out, int out_size) {
    const float* X  = (const float*)d_in[0];
    const float* MR = (const float*)d_in[1];
    const float* MI = (const float*)d_in[2];
    float* OUT = (float*)d_out;
    const int M = in_sizes[0] / KDIM;   // 128000

    build_B_kernel<<<(NPAD * KDIM) / 256, 256>>>(MR, MI);

    cudaFuncSetAttribute(rfft_wmma_kernel, cudaFuncAttributeMaxDynamicSharedMemorySize, SMEM_BYTES);
    dim3 grid(6, M / BM);   // 5 full 96-wide columns + 1 48-wide tail
    rfft_wmma_kernel<<<grid, THREADS, SMEM_BYTES>>>(X, OUT, M);
}

// round 15
// speedup vs baseline: 2.3416x; 2.1212x over previous
#include <cuda_runtime.h>
#include <cstdint>
#include <cstddef>
#include <math.h>

#define NFFT 512
#define NRE 257
#define ROWS_PER_CTA 4
#define TPR 64
#define THREADS (ROWS_PER_CTA * TPR)   // 256
#define BUF 576                        // padded row buffer (max skewed addr 567)

// twiddle table: tw[i] = exp(-2*pi*i*I/512)
__device__ float g_twre[NFFT];
__device__ float g_twim[NFFT];

__global__ void build_tw() {
    int i = blockIdx.x * blockDim.x + threadIdx.x;
    if (i < NFFT) {
        double a = -2.0 * 3.14159265358979323846 * (double)i / (double)NFFT;
        g_twre[i] = (float)cos(a);
        g_twim[i] = (float)sin(a);
    }
}

// 8-point DFT (DIF, natural-order outputs): z[m] = sum_j a[j] * W8^{j*m}
__device__ __forceinline__ void dft8(float* re, float* im) {
    const float C = 0.70710678118654752f;
    float s0r=re[0]+re[4], s0i=im[0]+im[4];
    float d0r=re[0]-re[4], d0i=im[0]-im[4];
    float s1r=re[1]+re[5], s1i=im[1]+im[5];
    float d1r=re[1]-re[5], d1i=im[1]-im[5];
    float s2r=re[2]+re[6], s2i=im[2]+im[6];
    float d2r=re[2]-re[6], d2i=im[2]-im[6];
    float s3r=re[3]+re[7], s3i=im[3]+im[7];
    float d3r=re[3]-re[7], d3i=im[3]-im[7];
    float t;
    // d1 *= W8^1 = C*(1-i)
    t = C*(d1r + d1i); d1i = C*(d1i - d1r); d1r = t;
    // d2 *= W8^2 = -i
    t = d2i; d2i = -d2r; d2r = t;
    // d3 *= W8^3 = -C*(1+i)
    t = C*(d3i - d3r); d3i = -C*(d3r + d3i); d3r = t;
    // FFT4 on s -> z0, z2, z4, z6
    float u0r=s0r+s2r, u0i=s0i+s2i;
    float u2r=s0r-s2r, u2i=s0i-s2i;
    float u1r=s1r+s3r, u1i=s1i+s3i;
    float u3r=s1r-s3r, u3i=s1i-s3i;
    re[0]=u0r+u1r; im[0]=u0i+u1i;
    re[4]=u0r-u1r; im[4]=u0i-u1i;
    re[2]=u2r+u3i; im[2]=u2i-u3r;      // u2 - i*u3
    re[6]=u2r-u3i; im[6]=u2i+u3r;      // u2 + i*u3
    // FFT4 on d -> z1, z3, z5, z7
    float v0r=d0r+d2r, v0i=d0i+d2i;
    float v2r=d0r-d2r, v2i=d0i-d2i;
    float v1r=d1r+d3r, v1i=d1i+d3i;
    float v3r=d1r-d3r, v3i=d1i-d3i;
    re[1]=v0r+v1r; im[1]=v0i+v1i;
    re[5]=v0r-v1r; im[5]=v0i-v1i;
    re[3]=v2r+v3i; im[3]=v2i-v3r;
    re[7]=v2r-v3i; im[7]=v2i+v3r;
}

__global__ void __launch_bounds__(THREADS)
rfft512_kernel(const float* __restrict__ X, float* __restrict__ OUT, int Mrows) {
    __shared__ float sAre[ROWS_PER_CTA][BUF], sAim[ROWS_PER_CTA][BUF];
    __shared__ float sBre[ROWS_PER_CTA][BUF], sBim[ROWS_PER_CTA][BUF];
    __shared__ float twre[NFFT], twim[NFFT];

    const int tid = threadIdx.x;
    for (int i = tid; i < NFFT; i += THREADS) { twre[i] = g_twre[i]; twim[i] = g_twim[i]; }

    const int r = tid >> 6;       // row within CTA
    const int u = tid & 63;       // thread within row
    const size_t row = (size_t)blockIdx.x * ROWS_PER_CTA + r;
    const float* xp = X + row * NFFT;

    float re[8], im[8];

    // ---- stage 0: load (stride 64), DFT8 over j, twiddle W512^{u*m} ----
#pragma unroll
    for (int j = 0; j < 8; j++) { re[j] = __ldg(xp + u + 64 * j); im[j] = 0.f; }
    dft8(re, im);
    __syncthreads();   // twiddle table ready
#pragma unroll
    for (int m = 0; m < 8; m++) {
        const float tr = twre[u * m], ti = twim[u * m];   // m=0 -> tw[0]=(1,0)
        const float orr = re[m] * tr - im[m] * ti;
        const float oi  = re[m] * ti + im[m] * tr;
        const int adr = u + 72 * m;                        // idx u+64m, skew +8m
        sAre[r][adr] = orr; sAim[r][adr] = oi;
    }
    __syncthreads();

    // ---- stage 1: b=m0=u>>3, t2=u&7; DFT8 over j (stride 8), twiddle W64^{t2*m1} ----
    {
        const int b = u >> 3, t2 = u & 7;
#pragma unroll
        for (int j = 0; j < 8; j++) {
            const int adr = 72 * b + t2 + 8 * j;
            re[j] = sAre[r][adr]; im[j] = sAim[r][adr];
        }
        dft8(re, im);
#pragma unroll
        for (int m1 = 0; m1 < 8; m1++) {
            const float tr = twre[8 * t2 * m1], ti = twim[8 * t2 * m1];
            const float orr = re[m1] * tr - im[m1] * ti;
            const float oi  = re[m1] * ti + im[m1] * tr;
            const int adr = 72 * b + 8 * m1 + ((t2 + m1) & 7);   // conflict-free both ways
            sBre[r][adr] = orr; sBim[r][adr] = oi;
        }
    }
    __syncthreads();

    // ---- stage 2: m0=u>>3, m1=u&7; DFT8 over t2; k = m0 + 8*m1 + 64*m2 ----
    {
        const int m0 = u >> 3, m1 = u & 7;
#pragma unroll
        for (int j = 0; j < 8; j++) {
            const int adr = 72 * m0 + 8 * m1 + ((j + m1) & 7);
            re[j] = sBre[r][adr]; im[j] = sBim[r][adr];
        }
        dft8(re, im);
        const int klow = m0 + 8 * m1;
#pragma unroll
        for (int m2 = 0; m2 < 4; m2++) {                    // k = klow + 64*m2 <= 255
            sAre[r][klow + 64 * m2] = re[m2];
            sAim[r][klow + 64 * m2] = im[m2];
        }
        if (u == 0) { sAre[r][256] = re[4]; sAim[r][256] = im[4]; }  // k = 256
    }
    __syncthreads();

    // ---- coalesced store: re plane then im plane ----
    float* outre = OUT + row * NRE;
    float* outim = OUT + (size_t)Mrows * NRE + row * NRE;
#pragma unroll
    for (int c = 0; c < 5; c++) {
        const int k = u + 64 * c;
        if (k < NRE) {
            outre[k] = sAre[r][k];
            outim[k] = sAim[r][k];
        }
    }
}

extern "C" void kernel_launch(void* const* d_in, const int* in_sizes, int n_in,
                              void* d_out, int out_size) {
    const float* X = (const float*)d_in[0];
    float* OUT = (float*)d_out;
    const int Mrows = in_sizes[0] / NFFT;   // 128000

    build_tw<<<2, 256>>>();
    rfft512_kernel<<<Mrows / ROWS_PER_CTA, THREADS>>>(X, OUT, Mrows);
}

// round 17
// speedup vs baseline: 3.3260x; 1.4204x over previous
#include <cuda_runtime.h>
#include <cstdint>
#include <cstddef>

#define NFFT 512
#define NRE 257
#define ROWS_PER_CTA 4
#define TPR 64
#define THREADS (ROWS_PER_CTA * TPR)   // 256
#define BUF 576                        // padded row buffer (max skewed addr 567)

#define TWO_PI_OVER_N (6.2831853071795864769f / 512.0f)

// 8-point DFT (DIF, natural-order outputs): z[m] = sum_j a[j] * W8^{j*m}
__device__ __forceinline__ void dft8(float* re, float* im) {
    const float C = 0.70710678118654752f;
    float s0r=re[0]+re[4], s0i=im[0]+im[4];
    float d0r=re[0]-re[4], d0i=im[0]-im[4];
    float s1r=re[1]+re[5], s1i=im[1]+im[5];
    float d1r=re[1]-re[5], d1i=im[1]-im[5];
    float s2r=re[2]+re[6], s2i=im[2]+im[6];
    float d2r=re[2]-re[6], d2i=im[2]-im[6];
    float s3r=re[3]+re[7], s3i=im[3]+im[7];
    float d3r=re[3]-re[7], d3i=im[3]-im[7];
    float t;
    t = C*(d1r + d1i); d1i = C*(d1i - d1r); d1r = t;     // * W8^1
    t = d2i; d2i = -d2r; d2r = t;                        // * -i
    t = C*(d3i - d3r); d3i = -C*(d3r + d3i); d3r = t;    // * W8^3
    float u0r=s0r+s2r, u0i=s0i+s2i;
    float u2r=s0r-s2r, u2i=s0i-s2i;
    float u1r=s1r+s3r, u1i=s1i+s3i;
    float u3r=s1r-s3r, u3i=s1i-s3i;
    re[0]=u0r+u1r; im[0]=u0i+u1i;
    re[4]=u0r-u1r; im[4]=u0i-u1i;
    re[2]=u2r+u3i; im[2]=u2i-u3r;
    re[6]=u2r-u3i; im[6]=u2i+u3r;
    float v0r=d0r+d2r, v0i=d0i+d2i;
    float v2r=d0r-d2r, v2i=d0i-d2i;
    float v1r=d1r+d3r, v1i=d1i+d3i;
    float v3r=d1r-d3r, v3i=d1i-d3i;
    re[1]=v0r+v1r; im[1]=v0i+v1i;
    re[5]=v0r-v1r; im[5]=v0i-v1i;
    re[3]=v2r+v3i; im[3]=v2i-v3r;
    re[7]=v2r-v3i; im[7]=v2i+v3r;
}

// Apply w^m (m = 1..7) to elements 1..7 via complex power recurrence.
__device__ __forceinline__ void twiddle7(float* re, float* im, float wc, float ws) {
    float cr = wc, ci = ws;     // current power w^1
#pragma unroll
    for (int m = 1; m < 8; m++) {
        const float nr = re[m] * cr - im[m] * ci;
        const float ni = re[m] * ci + im[m] * cr;
        re[m] = nr; im[m] = ni;
        const float tr = cr * wc - ci * ws;               // advance to w^{m+1}
        ci = cr * ws + ci * wc;
        cr = tr;
    }
}

__global__ void __launch_bounds__(THREADS)
rfft512_kernel(const float* __restrict__ X, float* __restrict__ OUT, int Mrows) {
    __shared__ float2 sA[ROWS_PER_CTA][BUF];
    __shared__ float2 sB[ROWS_PER_CTA][BUF];

    const int tid = threadIdx.x;
    const int r = tid >> 6;       // row within CTA
    const int u = tid & 63;       // thread within row
    const size_t row = (size_t)blockIdx.x * ROWS_PER_CTA + r;
    const float* xp = X + row * NFFT;

    float re[8], im[8];

    // ---- stage 0: load (stride 64), DFT8, twiddle W512^{u*m} ----
#pragma unroll
    for (int j = 0; j < 8; j++) { re[j] = __ldg(xp + u + 64 * j); im[j] = 0.f; }
    dft8(re, im);
    {
        float ws, wc;
        __sincosf(-TWO_PI_OVER_N * (float)u, &ws, &wc);
        twiddle7(re, im, wc, ws);
    }
#pragma unroll
    for (int m = 0; m < 8; m++)
        sA[r][u + 72 * m] = make_float2(re[m], im[m]);
    __syncthreads();

    // ---- stage 1: b=u>>3, t2=u&7; DFT8 over j (stride 8), twiddle W64^{t2*m1} ----
    {
        const int b = u >> 3, t2 = u & 7;
#pragma unroll
        for (int j = 0; j < 8; j++) {
            const float2 v = sA[r][72 * b + t2 + 8 * j];
            re[j] = v.x; im[j] = v.y;
        }
        dft8(re, im);
        float ws, wc;
        __sincosf(-TWO_PI_OVER_N * (float)(8 * t2), &ws, &wc);
        twiddle7(re, im, wc, ws);
#pragma unroll
        for (int m1 = 0; m1 < 8; m1++)
            sB[r][72 * b + 8 * m1 + ((t2 + m1) & 7)] = make_float2(re[m1], im[m1]);
    }
    __syncthreads();

    // ---- stage 2: m0=u>>3, m1=u&7; DFT8 over j; k = m0 + 8*m1 + 64*m2 ----
    {
        const int m0 = u >> 3, m1 = u & 7;
#pragma unroll
        for (int j = 0; j < 8; j++) {
            const float2 v = sB[r][72 * m0 + 8 * m1 + ((j + m1) & 7)];
            re[j] = v.x; im[j] = v.y;
        }
        dft8(re, im);
        const int klow = m0 + 8 * m1;
#pragma unroll
        for (int m2 = 0; m2 < 4; m2++)                     // k = klow + 64*m2 <= 255
            sA[r][klow + 64 * m2] = make_float2(re[m2], im[m2]);
        if (u == 0) sA[r][256] = make_float2(re[4], im[4]);   // k = 256
    }
    __syncthreads();

    // ---- coalesced store: re plane then im plane ----
    float* outre = OUT + row * NRE;
    float* outim = OUT + (size_t)Mrows * NRE + row * NRE;
#pragma unroll
    for (int c = 0; c < 5; c++) {
        const int k = u + 64 * c;
        if (k < NRE) {
            const float2 v = sA[r][k];
            outre[k] = v.x;
            outim[k] = v.y;
        }
    }
}

extern "C" void kernel_launch(void* const* d_in, const int* in_sizes, int n_in,
                              void* d_out, int out_size) {
    const float* X = (const float*)d_in[0];
    float* OUT = (float*)d_out;
    const int Mrows = in_sizes[0] / NFFT;   // 128000

    rfft512_kernel<<<Mrows / ROWS_PER_CTA, THREADS>>>(X, OUT, Mrows);
}